// round 7
// baseline (speedup 1.0000x reference)
#include <cuda_runtime.h>

#define FULLMASK 0xffffffffu
typedef unsigned long long ull;

// ---------- packed f32x2 helpers (Blackwell sm_103a) ----------
__device__ __forceinline__ ull pk2(float a, float b) {
    ull r;
    asm("mov.b64 %0, {%1, %2};" : "=l"(r) : "f"(a), "f"(b));
    return r;
}
__device__ __forceinline__ float2 upk2(ull v) {
    float2 r;
    asm("mov.b64 {%0, %1}, %2;" : "=f"(r.x), "=f"(r.y) : "l"(v));
    return r;
}
__device__ __forceinline__ ull dup2(float a) { return pk2(a, a); }

__device__ __forceinline__ ull ffma2(ull a, ull b, ull c) {
    ull d;
    asm("fma.rn.f32x2 %0, %1, %2, %3;" : "=l"(d) : "l"(a), "l"(b), "l"(c));
    return d;
}
__device__ __forceinline__ ull add2(ull a, ull b) {
    ull d;
    asm("add.rn.f32x2 %0, %1, %2;" : "=l"(d) : "l"(a), "l"(b));
    return d;
}

// tanh(x) = 1 - 2/(exp(2x)+1) via MUFU.EX2 + MUFU.RCP (abs err ~1e-7)
__device__ __forceinline__ float tanh_fast(float xx) {
    float e;
    asm("ex2.approx.f32 %0, %1;" : "=f"(e) : "f"(xx * 2.8853900817779268f));
    float r;
    asm("rcp.approx.f32 %0, %1;" : "=f"(r) : "f"(e + 1.0f));
    return fmaf(-2.0f, r, 1.0f);
}

// 64-thread CTA (2 warps), 2 elements, 2-D blocked layer 2.
// Thread L = (r = L>>3 in 0..7, c = L&7):
//   layer 1: h1 unit L for both elems (1 fma + 1 tanh each), STS
//   layer 2: 8x8 W2 block rows[8r,+8) x cols[8c,+8) in 32 packed regs;
//            per elem: 2 LDS.128 (own 8 h) + 32 ffma2 (4 parallel chains)
//   reduce:  2 split-butterfly rounds in-warp (thread ends owning one col-pair)
//            + ONE cross-warp STS.128/LDS.128 swap (gives both elems to both warps)
//   tail:    bias + 4 tanh + packed f32x2 warp butterfly -> both gamma_dots
//            on every thread. Only 2 __syncthreads per step.
__global__ void __launch_bounds__(64, 7)
maxwell_ffnn_kernel(const float* __restrict__ x,
                    const float* __restrict__ W1,
                    const float* __restrict__ b1,
                    const float* __restrict__ W2,
                    const float* __restrict__ b2,
                    const float* __restrict__ W3,
                    const float* __restrict__ b3,
                    float* __restrict__ out) {
    __shared__ __align__(16) float hbuf[2][2][64];        // [parity][elem][unit]
    __shared__ __align__(16) ulonglong2 pbuf[2][64];      // [parity][thread]

    const int L   = threadIdx.x;          // 0..63
    const int R0  = (L >> 3) * 8;         // row block base (0..56)
    const int c8  = (L & 7) * 8;          // col block base
    const bool o1 = (L >> 3) & 1;         // split-round selectors
    const bool o2 = (L >> 4) & 1;
    const int P   = (o1 ? 2 : 0) + (o2 ? 1 : 0);
    const int j0  = c8 + 2 * P;           // owned col pair (j0, j0+1)

    // ---- loop-invariant weights ----
    const float w1a = __ldg(&W1[L]);
    const float w1b = __ldg(&W1[64 + L]);
    const float b1v = __ldg(&b1[L]);

    ull w2b[32];                          // [i*4+p] = (W2[R0+i][c8+2p], W2[R0+i][c8+2p+1])
#pragma unroll
    for (int i = 0; i < 8; ++i)
#pragma unroll
        for (int p = 0; p < 4; ++p)
            w2b[i * 4 + p] = pk2(__ldg(&W2[(R0 + i) * 64 + c8 + 2 * p]),
                                 __ldg(&W2[(R0 + i) * 64 + c8 + 2 * p + 1]));

    const ull   b2p = pk2(__ldg(&b2[j0]), __ldg(&b2[j0 + 1]));
    const float w3x = __ldg(&W3[j0]);
    const float w3y = __ldg(&W3[j0 + 1]);
    const float b3v = __ldg(&b3[0]);

    const int e0 = blockIdx.x * 2;
    const float2* xp0 = (const float2*)(x + (size_t)e0 * 2048);
    const float2* xp1 = xp0 + 1024;
    float* op0 = out + (size_t)e0 * 1024;
    float* op1 = op0 + 1024;

    float gamma0 = 0.0f, gamma1 = 0.0f;
    float2 xv0 = __ldg(&xp0[0]);
    float2 xv1 = __ldg(&xp1[0]);
    const ull zero2 = pk2(0.0f, 0.0f);

#pragma unroll 2
    for (int t = 0; t < 1024; ++t) {
        const int par = t & 1;
        const float eps0 = xv0.x, dtn0 = xv0.y;
        const float eps1 = xv1.x, dtn1 = xv1.y;
        if (t < 1023) { xv0 = __ldg(&xp0[t + 1]); xv1 = __ldg(&xp1[t + 1]); }

        // ---- layer 1: unit L for both elements ----
        hbuf[par][0][L] = tanh_fast(fmaf(gamma0, w1b, fmaf(eps0, w1a, b1v)));
        hbuf[par][1][L] = tanh_fast(fmaf(gamma1, w1b, fmaf(eps1, w1a, b1v)));
        __syncthreads();

        // ---- layer 2 partials: 8x8 block, both elements ----
        ull part[2];
#pragma unroll
        for (int e = 0; e < 2; ++e) {
            const float4* hp = (const float4*)&hbuf[par][e][R0];
            const float4 ha = hp[0];
            const float4 hb = hp[1];
            ull a0 = zero2, a1 = zero2, a2 = zero2, a3 = zero2;
            {
                const ull d0 = dup2(ha.x), d1 = dup2(ha.y),
                          d2 = dup2(ha.z), d3 = dup2(ha.w);
                a0 = ffma2(d0, w2b[0],  a0); a1 = ffma2(d0, w2b[1],  a1);
                a2 = ffma2(d0, w2b[2],  a2); a3 = ffma2(d0, w2b[3],  a3);
                a0 = ffma2(d1, w2b[4],  a0); a1 = ffma2(d1, w2b[5],  a1);
                a2 = ffma2(d1, w2b[6],  a2); a3 = ffma2(d1, w2b[7],  a3);
                a0 = ffma2(d2, w2b[8],  a0); a1 = ffma2(d2, w2b[9],  a1);
                a2 = ffma2(d2, w2b[10], a2); a3 = ffma2(d2, w2b[11], a3);
                a0 = ffma2(d3, w2b[12], a0); a1 = ffma2(d3, w2b[13], a1);
                a2 = ffma2(d3, w2b[14], a2); a3 = ffma2(d3, w2b[15], a3);
            }
            {
                const ull d0 = dup2(hb.x), d1 = dup2(hb.y),
                          d2 = dup2(hb.z), d3 = dup2(hb.w);
                a0 = ffma2(d0, w2b[16], a0); a1 = ffma2(d0, w2b[17], a1);
                a2 = ffma2(d0, w2b[18], a2); a3 = ffma2(d0, w2b[19], a3);
                a0 = ffma2(d1, w2b[20], a0); a1 = ffma2(d1, w2b[21], a1);
                a2 = ffma2(d1, w2b[22], a2); a3 = ffma2(d1, w2b[23], a3);
                a0 = ffma2(d2, w2b[24], a0); a1 = ffma2(d2, w2b[25], a1);
                a2 = ffma2(d2, w2b[26], a2); a3 = ffma2(d2, w2b[27], a3);
                a0 = ffma2(d3, w2b[28], a0); a1 = ffma2(d3, w2b[29], a1);
                a2 = ffma2(d3, w2b[30], a2); a3 = ffma2(d3, w2b[31], a3);
            }

            // ---- in-warp split reduce over r (rounds xor8, xor16) ----
            // round 1: keep my P-base pair-set, receive partner's matching set
            ull s0 = o1 ? a0 : a2;
            ull s1 = o1 ? a1 : a3;
            ull k0 = o1 ? a2 : a0;
            ull k1 = o1 ? a3 : a1;
            k0 = add2(k0, __shfl_xor_sync(FULLMASK, s0, 8));
            k1 = add2(k1, __shfl_xor_sync(FULLMASK, s1, 8));
            // round 2
            ull ss = o2 ? k0 : k1;
            ull rr = o2 ? k1 : k0;
            part[e] = add2(rr, __shfl_xor_sync(FULLMASK, ss, 16));
        }

        // ---- one cross-warp exchange: both elements at once ----
        pbuf[par][L] = make_ulonglong2(part[0], part[1]);
        __syncthreads();
        const ulonglong2 q = pbuf[par][L ^ 32];
        const ull full0 = add2(add2(part[0], q.x), b2p);
        const ull full1 = add2(add2(part[1], q.y), b2p);

        // ---- layer-2 tanh + layer-3 dot (owned col pair, both elems) ----
        const float2 f0 = upk2(full0);
        const float2 f1 = upk2(full1);
        const float gp0 = fmaf(tanh_fast(f0.y), w3y, tanh_fast(f0.x) * w3x);
        const float gp1 = fmaf(tanh_fast(f1.y), w3y, tanh_fast(f1.x) * w3x);

        // ---- packed warp butterfly over 32 col-pairs ----
        ull g = pk2(gp0, gp1);
#pragma unroll
        for (int d = 1; d < 32; d <<= 1)
            g = add2(g, __shfl_xor_sync(FULLMASK, g, d));

        const float2 gd = upk2(g);
        gamma0 = fmaf(dtn0, gd.x + b3v, gamma0);
        gamma1 = fmaf(dtn1, gd.y + b3v, gamma1);

        // sigma = 2.5*eps - 2*gamma
        if (L == 0)  op0[t] = fmaf(-2.0f, gamma0, 2.5f * eps0);
        if (L == 33) op1[t] = fmaf(-2.0f, gamma1, 2.5f * eps1);
    }
}

extern "C" void kernel_launch(void* const* d_in, const int* in_sizes, int n_in,
                              void* d_out, int out_size) {
    (void)in_sizes; (void)n_in; (void)out_size;
    const float* x  = (const float*)d_in[0];
    const float* W1 = (const float*)d_in[1];
    const float* b1 = (const float*)d_in[2];
    const float* W2 = (const float*)d_in[3];
    const float* b2 = (const float*)d_in[4];
    const float* W3 = (const float*)d_in[5];
    const float* b3 = (const float*)d_in[6];
    float* out = (float*)d_out;

    // 2 elements per 64-thread CTA: 1024 CTAs = 2048 warps (13.8/SM, one wave)
    maxwell_ffnn_kernel<<<1024, 64>>>(x, W1, b1, W2, b2, W3, b3, out);
}

// round 8
// speedup vs baseline: 1.1795x; 1.1795x over previous
#include <cuda_runtime.h>

#define FULLMASK 0xffffffffu
typedef unsigned long long ull;

// ---------- packed f32x2 helpers (Blackwell sm_103a) ----------
__device__ __forceinline__ ull pk2(float a, float b) {
    ull r;
    asm("mov.b64 %0, {%1, %2};" : "=l"(r) : "f"(a), "f"(b));
    return r;
}
__device__ __forceinline__ float2 upk2(ull v) {
    float2 r;
    asm("mov.b64 {%0, %1}, %2;" : "=f"(r.x), "=f"(r.y) : "l"(v));
    return r;
}
__device__ __forceinline__ ull dup2(float a) { return pk2(a, a); }

__device__ __forceinline__ ull ffma2(ull a, ull b, ull c) {
    ull d;
    asm("fma.rn.f32x2 %0, %1, %2, %3;" : "=l"(d) : "l"(a), "l"(b), "l"(c));
    return d;
}
__device__ __forceinline__ ull add2(ull a, ull b) {
    ull d;
    asm("add.rn.f32x2 %0, %1, %2;" : "=l"(d) : "l"(a), "l"(b));
    return d;
}

// tanh with PRE-SCALED argument: zs = 2*log2(e)*z already folded into weights.
// tanh(z) = 1 - 2/(exp2(zs)+1)
__device__ __forceinline__ float tanh_pre(float zs) {
    float e;
    asm("ex2.approx.f32 %0, %1;" : "=f"(e) : "f"(zs));
    float r;
    asm("rcp.approx.f32 %0, %1;" : "=f"(r) : "f"(e + 1.0f));
    return fmaf(-2.0f, r, 1.0f);
}

// R4 layout (best known): one warp per CTA, TWO elements per warp.
// Lane l: h1 units (2l,2l+1); layer-2 cols l and l+32 with W2 in 128 packed regs.
// R8 deltas: wave-parity warp skew (anti-convoy), tanh scale folded into
// weights, depth-8 accumulator chains, dtn*b3 off-chain, unroll 2.
__global__ void __launch_bounds__(32)
maxwell_ffnn_kernel(const float* __restrict__ x,
                    const float* __restrict__ W1,
                    const float* __restrict__ b1,
                    const float* __restrict__ W2,
                    const float* __restrict__ b2,
                    const float* __restrict__ W3,
                    const float* __restrict__ b3,
                    float* __restrict__ out) {
    __shared__ __align__(16) ull hbuf[2][2][32];   // [parity][elem][lane]

    const int l  = threadIdx.x & 31;
    const int jA = l;
    const int jB = l + 32;
    const int u0 = 2 * l;

    const float K = 2.8853900817779268f;   // 2*log2(e), folded into pre-activations

    // ---- loop-invariant weights in registers (layer-1/2 pre-scaled by K) ----
    const ull c1a = pk2(K * __ldg(&W1[u0]),      K * __ldg(&W1[u0 + 1]));
    const ull c1b = pk2(K * __ldg(&W1[64 + u0]), K * __ldg(&W1[64 + u0 + 1]));
    const ull cb1 = pk2(K * __ldg(&b1[u0]),      K * __ldg(&b1[u0 + 1]));

    ull w2A[32], w2B[32];
#pragma unroll
    for (int s = 0; s < 32; ++s) {
        w2A[s] = pk2(K * __ldg(&W2[(2 * s) * 64 + jA]),
                     K * __ldg(&W2[(2 * s + 1) * 64 + jA]));
        w2B[s] = pk2(K * __ldg(&W2[(2 * s) * 64 + jB]),
                     K * __ldg(&W2[(2 * s + 1) * 64 + jB]));
    }
    const float b2A = K * __ldg(&b2[jA]);
    const float b2B = K * __ldg(&b2[jB]);
    const float w3A = __ldg(&W3[jA]);
    const float w3B = __ldg(&W3[jB]);
    const float b3v = __ldg(&b3[0]);

    const float2* xp0 = (const float2*)(x + (size_t)(blockIdx.x * 2) * 2048);
    const float2* xp1 = xp0 + 1024;
    float* op0 = out + (size_t)(blockIdx.x * 2) * 1024;
    float* op1 = op0 + 1024;

    // ---- anti-convoy skew: odd placement waves start ~380 cyc late ----
    if ((blockIdx.x / 148) & 1) {
        float z = (float)(threadIdx.x + 2);
        #pragma unroll
        for (int i = 0; i < 96; ++i) z = fmaf(z, 1.0000001f, 1.0f);
        if (z < 0.0f) op0[0] = z;   // never true (z > 0 always); keeps chain live
    }

    float gamma0 = 0.0f, gamma1 = 0.0f;
    float2 xv0 = __ldg(&xp0[0]);
    float2 xv1 = __ldg(&xp1[0]);
    const ull zero2 = pk2(0.0f, 0.0f);

#pragma unroll 2
    for (int t = 0; t < 1024; ++t) {
        const int par = t & 1;
        const float eps0 = xv0.x, dtn0 = xv0.y;
        const float eps1 = xv1.x, dtn1 = xv1.y;
        if (t < 1023) { xv0 = __ldg(&xp0[t + 1]); xv1 = __ldg(&xp1[t + 1]); }

        // off-chain: fold dtn*b3 into gamma early (layer1 uses the ORIGINAL gamma)
        const float gpre0 = fmaf(dtn0, b3v, gamma0);
        const float gpre1 = fmaf(dtn1, b3v, gamma1);

        // ---- layer 1 (both elements), pre-scaled weights -> tanh_pre ----
        {
            const ull p0 = ffma2(dup2(gamma0), c1b, ffma2(dup2(eps0), c1a, cb1));
            const ull p1 = ffma2(dup2(gamma1), c1b, ffma2(dup2(eps1), c1a, cb1));
            const float2 q0 = upk2(p0);
            const float2 q1 = upk2(p1);
            hbuf[par][0][l] = pk2(tanh_pre(q0.x), tanh_pre(q0.y));
            hbuf[par][1][l] = pk2(tanh_pre(q1.x), tanh_pre(q1.y));
        }
        __syncwarp();

        // ---- layer 2 + 3 partial (both elements, depth-8 chains) ----
        float gp[2];
#pragma unroll
        for (int e = 0; e < 2; ++e) {
            const ulonglong2* hp = (const ulonglong2*)&hbuf[par][e][0];
            ull A0 = pk2(b2A, 0.0f), A1 = zero2, A2 = zero2, A3 = zero2;
            ull B0 = pk2(b2B, 0.0f), B1 = zero2, B2 = zero2, B3 = zero2;
#pragma unroll
            for (int k = 0; k < 8; ++k) {
                const ulonglong2 ha = hp[2 * k];
                const ulonglong2 hb = hp[2 * k + 1];
                A0 = ffma2(ha.x, w2A[4 * k],     A0);
                B0 = ffma2(ha.x, w2B[4 * k],     B0);
                A1 = ffma2(ha.y, w2A[4 * k + 1], A1);
                B1 = ffma2(ha.y, w2B[4 * k + 1], B1);
                A2 = ffma2(hb.x, w2A[4 * k + 2], A2);
                B2 = ffma2(hb.x, w2B[4 * k + 2], B2);
                A3 = ffma2(hb.y, w2A[4 * k + 3], A3);
                B3 = ffma2(hb.y, w2B[4 * k + 3], B3);
            }
            const float2 aA = upk2(add2(add2(A0, A1), add2(A2, A3)));
            const float2 aB = upk2(add2(add2(B0, B1), add2(B2, B3)));
            const float h2A = tanh_pre(aA.x + aA.y);
            const float h2B = tanh_pre(aB.x + aB.y);
            gp[e] = fmaf(h2A, w3A, h2B * w3B);
        }

        // ---- warp-wide sums: interleaved butterflies (latencies overlap) ----
#pragma unroll
        for (int d = 1; d < 32; d <<= 1) {
            const float s0 = __shfl_xor_sync(FULLMASK, gp[0], d);
            const float s1 = __shfl_xor_sync(FULLMASK, gp[1], d);
            gp[0] += s0;
            gp[1] += s1;
        }

        // ---- gamma update + output ----
        gamma0 = fmaf(dtn0, gp[0], gpre0);
        gamma1 = fmaf(dtn1, gp[1], gpre1);

        // sigma = 0.5*eps + 2*(eps - gamma) = 2.5*eps - 2*gamma
        if (l == 0) op0[t] = fmaf(-2.0f, gamma0, 2.5f * eps0);
        if (l == 1) op1[t] = fmaf(-2.0f, gamma1, 2.5f * eps1);
    }
}

extern "C" void kernel_launch(void* const* d_in, const int* in_sizes, int n_in,
                              void* d_out, int out_size) {
    (void)in_sizes; (void)n_in; (void)out_size;
    const float* x  = (const float*)d_in[0];
    const float* W1 = (const float*)d_in[1];
    const float* b1 = (const float*)d_in[2];
    const float* W2 = (const float*)d_in[3];
    const float* b2 = (const float*)d_in[4];
    const float* W3 = (const float*)d_in[5];
    const float* b3 = (const float*)d_in[6];
    float* out = (float*)d_out;

    // 2 elements per warp: 1024 single-warp CTAs (~7/SM, single wave)
    maxwell_ffnn_kernel<<<1024, 32>>>(x, W1, b1, W2, b2, W3, b3, out);
}